// round 15
// baseline (speedup 1.0000x reference)
#include <cuda_runtime.h>
#include <cuda_fp16.h>
#include <cstdint>

// ---------------- problem dims ----------------
#define BATCH 8
#define CIN   256
#define COUT  256
#define IMH   64
#define IMW   64
#define PLANE 4096        // IMH*IMW
#define CK    2304        // CIN*9
#define NOFF  4608        // 2*CK
#define NSC   2304
#define NDCN  589824      // COUT*CK
#define NTOT  596736
#define NCHUNK 36         // 2304 kk / 64 per chunk
#define AIMG  16384       // one 32-k A image: [256 o x 32 k] fp16, swizzled
#define ABYTES 32768      // per-K64-chunk A: two consecutive images
#define BIMG  2048        // one 32-k B image: [32 px x 32 k] fp16, swizzled
#define BBYTES 4096       // per-K64-chunk B: two images
#define PART_Q 8          // k_offscale CIN split

// ---------------- smem layout (dynamic) ----------------
#define SO_OY    0        // float[64]
#define SO_OX    256
#define SO_SC    512
#define SO_IDX   768      // int4[576]
#define SO_W     9984     // float4[576]
#define SO_A     19456    // 2 x 32768
#define SO_B     84992    // 2 x 4096
#define SMEM_TOTAL 93184  // x2 CTAs = 186 KB < 228 KB

// ---------------- device scratch ----------------
__device__ unsigned int g_absmax[4];     // [0]=w_off [1]=w_scale [2]=w_dcn [3]=x
__device__ float g_woffq[NOFF];
__device__ float g_wscq[NSC];
__device__ __align__(128) unsigned char g_wh[(size_t)NCHUNK * ABYTES]; // swizzled fp16 codes
__device__ float g_part[PART_Q * BATCH * 3 * PLANE]; // offscale partials

// ---------------- helpers ----------------
__device__ __forceinline__ uint32_t smem_u32(const void* p) {
    uint32_t a;
    asm("{ .reg .u64 t; cvta.to.shared.u64 t, %1; cvt.u32.u64 %0, t; }" : "=r"(a) : "l"(p));
    return a;
}
__device__ __forceinline__ void ldsm4(uint32_t* r, uint32_t addr) {
    asm volatile("ldmatrix.sync.aligned.m8n8.x4.shared.b16 {%0,%1,%2,%3}, [%4];"
                 : "=r"(r[0]), "=r"(r[1]), "=r"(r[2]), "=r"(r[3]) : "r"(addr));
}
__device__ __forceinline__ void mma_f16(float* d, const uint32_t* a, uint32_t b0, uint32_t b1) {
    asm volatile("mma.sync.aligned.m16n8k16.row.col.f32.f16.f16.f32 "
                 "{%0,%1,%2,%3}, {%4,%5,%6,%7}, {%8,%9}, {%0,%1,%2,%3};"
                 : "+f"(d[0]), "+f"(d[1]), "+f"(d[2]), "+f"(d[3])
                 : "r"(a[0]), "r"(a[1]), "r"(a[2]), "r"(a[3]), "r"(b0), "r"(b1));
}
__device__ __forceinline__ void cp16(uint32_t dst, const void* src) {
    asm volatile("cp.async.cg.shared.global [%0], [%1], 16;" :: "r"(dst), "l"(src));
}
#define CP_COMMIT() asm volatile("cp.async.commit_group;")
#define CP_WAIT0()  asm volatile("cp.async.wait_group 0;")

// ---------------- kernel 0: reset absmax ----------------
__global__ void k_zero() {
    if (threadIdx.x < 4) g_absmax[threadIdx.x] = 0u;
}

// ---------------- kernel 1: per-tensor abs-max (weights) ----------------
__global__ void k_absmax(const float* __restrict__ w_off,
                         const float* __restrict__ w_scale,
                         const float* __restrict__ w_dcn) {
    int i = blockIdx.x * blockDim.x + threadIdx.x;
    float v = 0.f; int slot = 4;
    if (i < NOFF)            { v = fabsf(w_off[i]);              slot = 0; }
    else if (i < NOFF + NSC) { v = fabsf(w_scale[i - NOFF]);     slot = 1; }
    else if (i < NTOT)       { v = fabsf(w_dcn[i - NOFF - NSC]); slot = 2; }
    #pragma unroll
    for (int s = 0; s < 3; s++) {
        float m = (slot == s) ? v : 0.f;
        #pragma unroll
        for (int o = 16; o > 0; o >>= 1)
            m = fmaxf(m, __shfl_xor_sync(0xffffffffu, m, o));
        if ((threadIdx.x & 31) == 0 && m > 0.f)
            atomicMax(&g_absmax[s], __float_as_uint(m));
    }
}

// ---------------- kernel 1b: abs-max over x ----------------
__global__ void k_xmax(const float4* __restrict__ x4) {
    int i = blockIdx.x * blockDim.x + threadIdx.x;
    float m = 0.f;
    const int n4 = BATCH * CIN * PLANE / 4;
    for (int idx = i; idx < n4; idx += gridDim.x * blockDim.x) {
        float4 v = x4[idx];
        m = fmaxf(m, fmaxf(fmaxf(fabsf(v.x), fabsf(v.y)),
                           fmaxf(fabsf(v.z), fabsf(v.w))));
    }
    #pragma unroll
    for (int o = 16; o > 0; o >>= 1)
        m = fmaxf(m, __shfl_xor_sync(0xffffffffu, m, o));
    if ((threadIdx.x & 31) == 0 && m > 0.f)
        atomicMax(&g_absmax[3], __float_as_uint(m));
}

// ---------------- kernel 2: fake-quant ----------------
__device__ __forceinline__ float fq(float w, float s) {
    float q = rintf(w / s);
    q = fminf(fmaxf(q, -8.f), 7.f);
    return q * s;
}
__global__ void k_quant(const float* __restrict__ w_off,
                        const float* __restrict__ w_scale,
                        const float* __restrict__ w_dcn) {
    int i = blockIdx.x * blockDim.x + threadIdx.x;
    if (i >= NTOT) return;
    if (i < NOFF) {
        float s = fmaxf(__uint_as_float(g_absmax[0]), 1e-8f) / 7.0f;
        g_woffq[i] = fq(w_off[i], s);
    } else if (i < NOFF + NSC) {
        int j = i - NOFF;
        float s = fmaxf(__uint_as_float(g_absmax[1]), 1e-8f) / 7.0f;
        g_wscq[j] = fq(w_scale[j], s);
    } else {
        // w_dcn: INTEGER code (exact in fp16), swizzled smem image per 32-k
        // group: row o (64B), 16B-chunk c = ii>>3, swizzled c ^ ((o>>1)&3).
        int j = i - NOFF - NSC;
        float s = fmaxf(__uint_as_float(g_absmax[2]), 1e-8f) / 7.0f;
        float q = rintf(w_dcn[j] / s);
        q = fminf(fmaxf(q, -8.f), 7.f);
        int o  = j / CK, kk = j - o * CK;
        int ch = kk >> 5, ii = kk & 31;     // 32-k image index
        unsigned char* base = g_wh + (size_t)ch * AIMG;
        int addr = o * 64 + (((ii >> 3) ^ ((o >> 1) & 3)) * 16) + (ii & 7) * 2;
        *(__half*)(base + addr) = __float2half_rn(q);
    }
}

// ---------------- kernel 3: offset/scale conv, CIN split 8-way ----------------
__global__ void __launch_bounds__(128) k_offscale(const float* __restrict__ x) {
    __shared__ float sw0[288], sw1[288], sws[288];
    int tid = threadIdx.x;
    int c0 = blockIdx.z * 32;
    for (int i = tid; i < 288; i += 128) {
        sw0[i] = g_woffq[c0 * 9 + i];
        sw1[i] = g_woffq[CK + c0 * 9 + i];
        sws[i] = g_wscq[c0 * 9 + i];
    }
    __syncthreads();

    int b  = blockIdx.y;
    int y  = blockIdx.x * 2 + (tid >> 6);
    int xc = tid & 63;
    float a0 = 0.f, a1 = 0.f, a2 = 0.f;
    const float* xb = x + ((size_t)b * CIN + c0) * PLANE;

    for (int c = 0; c < 32; c++) {
        const float* xp = xb + c * PLANE;
        const float* w0 = sw0 + c * 9;
        const float* w1 = sw1 + c * 9;
        const float* ws = sws + c * 9;
        #pragma unroll
        for (int dy = -1; dy <= 1; dy++) {
            int yy = y + dy;
            bool yv = ((unsigned)yy < 64u);
            #pragma unroll
            for (int dx = -1; dx <= 1; dx++) {
                int xx = xc + dx;
                float v = (yv && (unsigned)xx < 64u) ? xp[yy * IMW + xx] : 0.f;
                int t = (dy + 1) * 3 + (dx + 1);
                a0 = fmaf(w0[t], v, a0);
                a1 = fmaf(w1[t], v, a1);
                a2 = fmaf(ws[t], v, a2);
            }
        }
    }
    int p = y * IMW + xc;
    float* gp = g_part + ((size_t)(blockIdx.z * BATCH + b) * 3) * PLANE;
    gp[p]             = a0;
    gp[PLANE + p]     = a1;
    gp[2 * PLANE + p] = a2;
}

// ---------------- kernel 4: gather + fp16 mma.sync GEMM ----------------
// Block = (b, y, ph): 256 o x 32 px (px half ph). 1024 CTAs -> near-perfect
// wave balance (vs 512-CTA grid's 15.6% busiest-SM excess). 8 warps: warp w
// -> o-tile 64 ((w&3)*64), px-tile 16 ((w>>2)*16). 2 CTAs/SM.
__global__ void __launch_bounds__(256, 2) k_main(const float* __restrict__ x,
                                                 const float* __restrict__ b_off,
                                                 const float* __restrict__ b_scale,
                                                 const float* __restrict__ b_dcn,
                                                 float* __restrict__ out) {
    extern __shared__ __align__(1024) unsigned char sm[];
    uint32_t smb = smem_u32(sm);
    const int tid = threadIdx.x;
    const int wid = tid >> 5, lid = tid & 31;
    const int y = blockIdx.x, b = blockIdx.y, ph = blockIdx.z;

    // prologue: kick A chunk 0 (32 KB) while stage 0 runs
    {
        const unsigned char* src = g_wh;
        for (int i = 0; i < 8; i++) {
            int idx = tid + 256 * i;
            cp16(smb + SO_A + idx * 16, src + idx * 16);
        }
        CP_COMMIT();
    }

    // stage 0a: combine offscale partials for this row's 64 px
    float* s_oy = (float*)(sm + SO_OY);
    float* s_ox = (float*)(sm + SO_OX);
    float* s_sc = (float*)(sm + SO_SC);
    if (tid < 64) {
        int p = y * IMW + tid;
        float oy = 0.f, ox = 0.f, sc = 0.f;
        #pragma unroll
        for (int q = 0; q < PART_Q; q++) {
            const float* gp = g_part + ((size_t)(q * BATCH + b) * 3) * PLANE;
            oy += gp[p];
            ox += gp[PLANE + p];
            sc += gp[2 * PLANE + p];
        }
        s_oy[tid] = oy + b_off[0];
        s_ox[tid] = ox + b_off[1];
        s_sc[tid] = fmaxf(sc + b_scale[0], 0.f);
    }
    __syncthreads();

    // stage 0b: bilinear records per (tap, px) — full 64 px (both halves use
    // identical tables; duplicated build cost is negligible)
    int4*   s_idx = (int4*)(sm + SO_IDX);
    float4* s_w   = (float4*)(sm + SO_W);
    for (int s = tid; s < 9 * IMW; s += 256) {
        int k  = s >> 6;
        int px = s & 63;
        float sc = s_sc[px];
        float ry = (float)(k / 3 - 1);
        float rx = (float)(k % 3 - 1);
        float py  = (float)y  + ry * sc + s_oy[px];
        float pxf = (float)px + rx * sc + s_ox[px];
        float y0 = floorf(py), x0 = floorf(pxf);
        float fy = py - y0, fx = pxf - x0;
        bool vy0 = (y0 >= 0.f)  && (y0 <= 63.f);
        bool vy1 = (y0 >= -1.f) && (y0 <= 62.f);
        bool vx0 = (x0 >= 0.f)  && (x0 <= 63.f);
        bool vx1 = (x0 >= -1.f) && (x0 <= 62.f);
        int iy0 = (int)fminf(fmaxf(y0,       0.f), 63.f);
        int iy1 = (int)fminf(fmaxf(y0 + 1.f, 0.f), 63.f);
        int ix0 = (int)fminf(fmaxf(x0,       0.f), 63.f);
        int ix1 = (int)fminf(fmaxf(x0 + 1.f, 0.f), 63.f);
        float w00 = (1.f - fy) * (1.f - fx) * ((vy0 && vx0) ? 1.f : 0.f);
        float w01 = (1.f - fy) * fx         * ((vy0 && vx1) ? 1.f : 0.f);
        float w10 = fy * (1.f - fx)         * ((vy1 && vx0) ? 1.f : 0.f);
        float w11 = fy * fx                 * ((vy1 && vx1) ? 1.f : 0.f);
        s_idx[s] = make_int4(iy0 * IMW + ix0, iy0 * IMW + ix1,
                             iy1 * IMW + ix0, iy1 * IMW + ix1);
        s_w[s] = make_float4(w00, w01, w10, w11);
    }
    __syncthreads();

    // per-thread constants
    const float amax = fmaxf(__uint_as_float(g_absmax[3]), 1e-20f);
    int eexp; frexpf(amax, &eexp);                 // amax = m * 2^eexp, m in [0.5,1)
    const float sB   = ldexpf(1.f, 11 - eexp);     // amax*sB in [1024, 2048)
    const float isB  = ldexpf(1.f, eexp - 11);     // exact inverse (power of 2)

    const float* xb = x + (size_t)b * CIN * PLANE;
    const int pxl   = tid & 31;               // B-producer local px (0..31)
    const int pxg   = ph * 32 + pxl;          // global px
    const int grp   = tid >> 5;               // kk group (4 consecutive kk)
    // STS: row pxl (64B), 16B-chunk c = grp>>1 swizzled by (pxl>>1)&3, 8B half
    const int bst   = pxl * 64 + (((grp >> 1) ^ ((pxl >> 1) & 3)) << 4)
                    + (grp & 1) * 8;

    const int o_tile  = (wid & 3) * 64;
    const int px_tile = (wid >> 2) * 16;      // local px tile (0 or 16)
    const int arow    = o_tile + (lid & 15);
    const int arow64  = arow * 64;
    const int asw     = ((lid & 15) >> 1) & 3;
    const int ahi     = lid >> 4;
    const int brow    = px_tile + (lid & 7) + ((lid >> 4) & 1) * 8; // local row 0..31
    const int brow64  = brow * 64;
    const int bsw     = (brow >> 1) & 3;
    const int bsel    = (lid >> 3) & 1;

    float acc[32];
    #pragma unroll
    for (int i = 0; i < 32; i++) acc[i] = 0.f;

    // gather 4 values for 32-k half `half` of K64 chunk jj
    auto gather4 = [&](int jj, int half, float* v) {
        int kk = jj * 64 + half * 32 + grp * 4;
        int c  = kk / 9;
        int t9 = kk - c * 9;
        #pragma unroll
        for (int u = 0; u < 4; u++) {
            int r = t9 * 64 + pxg;
            int4   iv = s_idx[r];
            float4 wv = s_w[r];
            const float* xp = xb + (size_t)c * PLANE;
            v[u] = __ldg(xp + iv.x) * wv.x + __ldg(xp + iv.y) * wv.y
                 + __ldg(xp + iv.z) * wv.z + __ldg(xp + iv.w) * wv.w;
            if (++t9 == 9) { t9 = 0; c++; }
        }
    };
    auto storeB = [&](int buf, int half, const float* v) {
        unsigned short h0 = __half_as_ushort(__float2half_rn(v[0] * sB));
        unsigned short h1 = __half_as_ushort(__float2half_rn(v[1] * sB));
        unsigned short h2 = __half_as_ushort(__float2half_rn(v[2] * sB));
        unsigned short h3 = __half_as_ushort(__float2half_rn(v[3] * sB));
        uint32_t w0 = ((uint32_t)h1 << 16) | (uint32_t)h0;
        uint32_t w1 = ((uint32_t)h3 << 16) | (uint32_t)h2;
        unsigned char* bbuf = sm + SO_B + buf * BBYTES + half * BIMG;
        *(uint2*)(bbuf + bst) = make_uint2(w0, w1);
    };

    // pre-loop: produce B chunk 0 (both halves) into buf 0; A(0) in flight
    {
        float v[4];
        gather4(0, 0, v);
        storeB(0, 0, v);
        gather4(0, 1, v);
        storeB(0, 1, v);
    }
    CP_WAIT0();
    __syncthreads();

    for (int j = 0; j < NCHUNK; j++) {
        // 1. prefetch A chunk j+1 (32 KB; async, no register dependency)
        if (j + 1 < NCHUNK) {
            const unsigned char* src = g_wh + (size_t)(j + 1) * ABYTES;
            uint32_t dst = smb + SO_A + ((j + 1) & 1) * ABYTES;
            #pragma unroll
            for (int i = 0; i < 8; i++) {
                int idx = tid + 256 * i;
                cp16(dst + idx * 16, src + idx * 16);
            }
        }
        CP_COMMIT();

        // 2. MMA over K64 chunk j: 4 k-steps (two 32-k images)
        {
            uint32_t Ab = smb + SO_A + (j & 1) * ABYTES;
            uint32_t Bb = smb + SO_B + (j & 1) * BBYTES;
            #pragma unroll
            for (int ks4 = 0; ks4 < 4; ks4++) {
                uint32_t Abh = Ab + (ks4 >> 1) * AIMG;
                uint32_t Bbh = Bb + (ks4 >> 1) * BIMG;
                int ks = ks4 & 1;
                uint32_t bb[4];
                int bc = ((ks * 2 + bsel) ^ bsw) * 16;
                ldsm4(bb, Bbh + brow64 + bc);
                int ac = ((ks * 2 + ahi) ^ asw) * 16;
                #pragma unroll
                for (int mt = 0; mt < 4; mt++) {
                    uint32_t a[4];
                    ldsm4(a, Abh + arow64 + mt * 1024 + ac);
                    #pragma unroll
                    for (int nt = 0; nt < 2; nt++)
                        mma_f16(acc + (mt * 2 + nt) * 4, a,
                                bb[2 * nt], bb[2 * nt + 1]);
                }
            }
        }

        // 3. gather + convert + publish B chunk j+1 (both halves) while the
        //    tensor queue drains
        if (j + 1 < NCHUNK) {
            float v[4];
            gather4(j + 1, 0, v);
            storeB((j + 1) & 1, 0, v);
            gather4(j + 1, 1, v);
            storeB((j + 1) & 1, 1, v);
        }

        // 4. A(j+1) complete (own copies) + block-wide publish of A and B
        CP_WAIT0();
        __syncthreads();
    }

    // ---------------- epilogue: scale + bias + store ----------------
    {
        float sdcn = fmaxf(__uint_as_float(g_absmax[2]), 1e-8f) / 7.0f;
        float sc = sdcn * isB;
        #pragma unroll
        for (int mt = 0; mt < 4; mt++) {
            int o0 = o_tile + mt * 16 + (lid >> 2);
            float bias0 = b_dcn[o0];
            float bias1 = b_dcn[o0 + 8];
            float* r0 = out + (((size_t)b * COUT + o0) * IMH + y) * IMW;
            float* r1 = r0 + 8 * (size_t)PLANE;
            #pragma unroll
            for (int nt = 0; nt < 2; nt++) {
                int pxo = ph * 32 + px_tile + nt * 8 + (lid & 3) * 2;
                const float* ac = acc + (mt * 2 + nt) * 4;
                float2 u0 = make_float2(ac[0] * sc + bias0, ac[1] * sc + bias0);
                float2 u1 = make_float2(ac[2] * sc + bias1, ac[3] * sc + bias1);
                *(float2*)(r0 + pxo) = u0;
                *(float2*)(r1 + pxo) = u1;
            }
        }
    }
}

// ---------------- launch ----------------
extern "C" void kernel_launch(void* const* d_in, const int* in_sizes, int n_in,
                              void* d_out, int out_size) {
    const float* x       = (const float*)d_in[0];
    const float* w_off   = (const float*)d_in[1];
    const float* b_off   = (const float*)d_in[2];
    const float* w_scale = (const float*)d_in[3];
    const float* b_scale = (const float*)d_in[4];
    const float* w_dcn   = (const float*)d_in[5];
    const float* b_dcn   = (const float*)d_in[6];
    float* out = (float*)d_out;

    static bool attr_done = false;
    if (!attr_done) {
        cudaFuncSetAttribute(k_main, cudaFuncAttributeMaxDynamicSharedMemorySize,
                             SMEM_TOTAL);
        attr_done = true;
    }

    int nb = (NTOT + 255) / 256;
    k_zero<<<1, 32>>>();
    k_absmax<<<nb, 256>>>(w_off, w_scale, w_dcn);
    k_xmax<<<512, 256>>>((const float4*)x);
    k_quant<<<nb, 256>>>(w_off, w_scale, w_dcn);
    k_offscale<<<dim3(IMH / 2, BATCH, PART_Q), 128>>>(x);
    k_main<<<dim3(IMH, BATCH, 2), 256, SMEM_TOTAL>>>(x, b_off, b_scale, b_dcn, out);
}

// round 16
// speedup vs baseline: 1.7058x; 1.7058x over previous
#include <cuda_runtime.h>
#include <cuda_fp16.h>
#include <cstdint>

// ---------------- problem dims ----------------
#define BATCH 8
#define CIN   256
#define COUT  256
#define IMH   64
#define IMW   64
#define PLANE 4096        // IMH*IMW
#define CK    2304        // CIN*9
#define NOFF  4608        // 2*CK
#define NSC   2304
#define NDCN  589824      // COUT*CK
#define NTOT  596736
#define NCHUNK 36         // 2304 kk / 64 per chunk (global)
#define KSPLIT 2          // K-split across CTAs
#define NCHUNK_PER 18     // chunks per CTA
#define AIMG  16384       // one 32-k A image: [256 o x 32 k] fp16, swizzled
#define ABYTES 32768      // per-K64-chunk A: two consecutive images
#define BIMG  4096        // one 32-k B image: [64 px x 32 k] fp16, swizzled
#define BBYTES 8192       // per-K64-chunk B: two images
#define PART_Q 8          // k_offscale CIN split

// ---------------- smem layout (dynamic) — IDENTICAL to R14 ----------------
#define SO_OY    0        // float[64]
#define SO_OX    256
#define SO_SC    512
#define SO_IDX   768      // int4[576]
#define SO_W     9984     // float4[576]
#define SO_A     19456    // 2 x 32768
#define SO_B     84992    // 2 x 8192
#define SMEM_TOTAL 101376 // x2 CTAs = 203 KB < 228 KB

// ---------------- device scratch ----------------
__device__ unsigned int g_absmax[4];     // [0]=w_off [1]=w_scale [2]=w_dcn [3]=x
__device__ float g_woffq[NOFF];
__device__ float g_wscq[NSC];
__device__ __align__(128) unsigned char g_wh[(size_t)NCHUNK * ABYTES]; // swizzled fp16 codes
__device__ float g_part[PART_Q * BATCH * 3 * PLANE]; // offscale partials

// ---------------- helpers ----------------
__device__ __forceinline__ uint32_t smem_u32(const void* p) {
    uint32_t a;
    asm("{ .reg .u64 t; cvta.to.shared.u64 t, %1; cvt.u32.u64 %0, t; }" : "=r"(a) : "l"(p));
    return a;
}
__device__ __forceinline__ void ldsm4(uint32_t* r, uint32_t addr) {
    asm volatile("ldmatrix.sync.aligned.m8n8.x4.shared.b16 {%0,%1,%2,%3}, [%4];"
                 : "=r"(r[0]), "=r"(r[1]), "=r"(r[2]), "=r"(r[3]) : "r"(addr));
}
__device__ __forceinline__ void mma_f16(float* d, const uint32_t* a, uint32_t b0, uint32_t b1) {
    asm volatile("mma.sync.aligned.m16n8k16.row.col.f32.f16.f16.f32 "
                 "{%0,%1,%2,%3}, {%4,%5,%6,%7}, {%8,%9}, {%0,%1,%2,%3};"
                 : "+f"(d[0]), "+f"(d[1]), "+f"(d[2]), "+f"(d[3])
                 : "r"(a[0]), "r"(a[1]), "r"(a[2]), "r"(a[3]), "r"(b0), "r"(b1));
}
__device__ __forceinline__ void cp16(uint32_t dst, const void* src) {
    asm volatile("cp.async.cg.shared.global [%0], [%1], 16;" :: "r"(dst), "l"(src));
}
#define CP_COMMIT() asm volatile("cp.async.commit_group;")
#define CP_WAIT0()  asm volatile("cp.async.wait_group 0;")

// ---------------- kernel 0: reset absmax ----------------
__global__ void k_zero() {
    if (threadIdx.x < 4) g_absmax[threadIdx.x] = 0u;
}

// ---------------- kernel 1: per-tensor abs-max (weights) ----------------
__global__ void k_absmax(const float* __restrict__ w_off,
                         const float* __restrict__ w_scale,
                         const float* __restrict__ w_dcn) {
    int i = blockIdx.x * blockDim.x + threadIdx.x;
    float v = 0.f; int slot = 4;
    if (i < NOFF)            { v = fabsf(w_off[i]);              slot = 0; }
    else if (i < NOFF + NSC) { v = fabsf(w_scale[i - NOFF]);     slot = 1; }
    else if (i < NTOT)       { v = fabsf(w_dcn[i - NOFF - NSC]); slot = 2; }
    #pragma unroll
    for (int s = 0; s < 3; s++) {
        float m = (slot == s) ? v : 0.f;
        #pragma unroll
        for (int o = 16; o > 0; o >>= 1)
            m = fmaxf(m, __shfl_xor_sync(0xffffffffu, m, o));
        if ((threadIdx.x & 31) == 0 && m > 0.f)
            atomicMax(&g_absmax[s], __float_as_uint(m));
    }
}

// ---------------- kernel 1b: abs-max over x ----------------
__global__ void k_xmax(const float4* __restrict__ x4) {
    int i = blockIdx.x * blockDim.x + threadIdx.x;
    float m = 0.f;
    const int n4 = BATCH * CIN * PLANE / 4;
    for (int idx = i; idx < n4; idx += gridDim.x * blockDim.x) {
        float4 v = x4[idx];
        m = fmaxf(m, fmaxf(fmaxf(fabsf(v.x), fabsf(v.y)),
                           fmaxf(fabsf(v.z), fabsf(v.w))));
    }
    #pragma unroll
    for (int o = 16; o > 0; o >>= 1)
        m = fmaxf(m, __shfl_xor_sync(0xffffffffu, m, o));
    if ((threadIdx.x & 31) == 0 && m > 0.f)
        atomicMax(&g_absmax[3], __float_as_uint(m));
}

// ---------------- kernel 2: fake-quant ----------------
__device__ __forceinline__ float fq(float w, float s) {
    float q = rintf(w / s);
    q = fminf(fmaxf(q, -8.f), 7.f);
    return q * s;
}
__global__ void k_quant(const float* __restrict__ w_off,
                        const float* __restrict__ w_scale,
                        const float* __restrict__ w_dcn) {
    int i = blockIdx.x * blockDim.x + threadIdx.x;
    if (i >= NTOT) return;
    if (i < NOFF) {
        float s = fmaxf(__uint_as_float(g_absmax[0]), 1e-8f) / 7.0f;
        g_woffq[i] = fq(w_off[i], s);
    } else if (i < NOFF + NSC) {
        int j = i - NOFF;
        float s = fmaxf(__uint_as_float(g_absmax[1]), 1e-8f) / 7.0f;
        g_wscq[j] = fq(w_scale[j], s);
    } else {
        // w_dcn: INTEGER code (exact in fp16), swizzled smem image per 32-k
        // group: row o (64B), 16B-chunk c = ii>>3, swizzled c ^ ((o>>1)&3).
        int j = i - NOFF - NSC;
        float s = fmaxf(__uint_as_float(g_absmax[2]), 1e-8f) / 7.0f;
        float q = rintf(w_dcn[j] / s);
        q = fminf(fmaxf(q, -8.f), 7.f);
        int o  = j / CK, kk = j - o * CK;
        int ch = kk >> 5, ii = kk & 31;     // 32-k image index
        unsigned char* base = g_wh + (size_t)ch * AIMG;
        int addr = o * 64 + (((ii >> 3) ^ ((o >> 1) & 3)) * 16) + (ii & 7) * 2;
        *(__half*)(base + addr) = __float2half_rn(q);
    }
}

// ---------------- kernel 2b: init output with bias ----------------
__global__ void k_binit(float* __restrict__ out, const float* __restrict__ b_dcn) {
    int i4 = blockIdx.x * blockDim.x + threadIdx.x;   // float4 index
    // out layout [b][o][y][x]: o = (i4*4 >> 12) & 255 = (i4 >> 10) & 255
    float bias = b_dcn[(i4 >> 10) & 255];
    ((float4*)out)[i4] = make_float4(bias, bias, bias, bias);
}

// ---------------- kernel 3: offset/scale conv, CIN split 8-way ----------------
__global__ void __launch_bounds__(128) k_offscale(const float* __restrict__ x) {
    __shared__ float sw0[288], sw1[288], sws[288];
    int tid = threadIdx.x;
    int c0 = blockIdx.z * 32;
    for (int i = tid; i < 288; i += 128) {
        sw0[i] = g_woffq[c0 * 9 + i];
        sw1[i] = g_woffq[CK + c0 * 9 + i];
        sws[i] = g_wscq[c0 * 9 + i];
    }
    __syncthreads();

    int b  = blockIdx.y;
    int y  = blockIdx.x * 2 + (tid >> 6);
    int xc = tid & 63;
    float a0 = 0.f, a1 = 0.f, a2 = 0.f;
    const float* xb = x + ((size_t)b * CIN + c0) * PLANE;

    for (int c = 0; c < 32; c++) {
        const float* xp = xb + c * PLANE;
        const float* w0 = sw0 + c * 9;
        const float* w1 = sw1 + c * 9;
        const float* ws = sws + c * 9;
        #pragma unroll
        for (int dy = -1; dy <= 1; dy++) {
            int yy = y + dy;
            bool yv = ((unsigned)yy < 64u);
            #pragma unroll
            for (int dx = -1; dx <= 1; dx++) {
                int xx = xc + dx;
                float v = (yv && (unsigned)xx < 64u) ? xp[yy * IMW + xx] : 0.f;
                int t = (dy + 1) * 3 + (dx + 1);
                a0 = fmaf(w0[t], v, a0);
                a1 = fmaf(w1[t], v, a1);
                a2 = fmaf(ws[t], v, a2);
            }
        }
    }
    int p = y * IMW + xc;
    float* gp = g_part + ((size_t)(blockIdx.z * BATCH + b) * 3) * PLANE;
    gp[p]             = a0;
    gp[PLANE + p]     = a1;
    gp[2 * PLANE + p] = a2;
}

// ---------------- kernel 4: gather + fp16 mma.sync GEMM, split-K ----------
// Block = (b, y, kh): 256 o x 64 px, K-chunks [18*kh, 18*kh+18). All smem
// layouts/swizzles byte-identical to the validated R14 kernel; only the chunk
// range and the atomic epilogue differ. 1024 CTAs -> 1.2% wave imbalance
// (vs 15.6% at 512). out pre-filled with bias by k_binit; epilogue RED.ADD.
__global__ void __launch_bounds__(256, 2) k_main(const float* __restrict__ x,
                                                 const float* __restrict__ b_off,
                                                 const float* __restrict__ b_scale,
                                                 float* __restrict__ out) {
    extern __shared__ __align__(1024) unsigned char sm[];
    uint32_t smb = smem_u32(sm);
    const int tid = threadIdx.x;
    const int wid = tid >> 5, lid = tid & 31;
    const int y = blockIdx.x, b = blockIdx.y;
    const int cbase = blockIdx.z * NCHUNK_PER;   // first K64 chunk for this CTA

    // prologue: kick A chunk cbase (32 KB) while stage 0 runs
    {
        const unsigned char* src = g_wh + (size_t)cbase * ABYTES;
        for (int i = 0; i < 8; i++) {
            int idx = tid + 256 * i;
            cp16(smb + SO_A + idx * 16, src + idx * 16);
        }
        CP_COMMIT();
    }

    // stage 0a: combine offscale partials for this row's 64 px
    float* s_oy = (float*)(sm + SO_OY);
    float* s_ox = (float*)(sm + SO_OX);
    float* s_sc = (float*)(sm + SO_SC);
    if (tid < 64) {
        int p = y * IMW + tid;
        float oy = 0.f, ox = 0.f, sc = 0.f;
        #pragma unroll
        for (int q = 0; q < PART_Q; q++) {
            const float* gp = g_part + ((size_t)(q * BATCH + b) * 3) * PLANE;
            oy += gp[p];
            ox += gp[PLANE + p];
            sc += gp[2 * PLANE + p];
        }
        s_oy[tid] = oy + b_off[0];
        s_ox[tid] = ox + b_off[1];
        s_sc[tid] = fmaxf(sc + b_scale[0], 0.f);
    }
    __syncthreads();

    // stage 0b: bilinear records per (tap, px)
    int4*   s_idx = (int4*)(sm + SO_IDX);
    float4* s_w   = (float4*)(sm + SO_W);
    for (int s = tid; s < 9 * IMW; s += 256) {
        int k  = s >> 6;
        int px = s & 63;
        float sc = s_sc[px];
        float ry = (float)(k / 3 - 1);
        float rx = (float)(k % 3 - 1);
        float py  = (float)y  + ry * sc + s_oy[px];
        float pxf = (float)px + rx * sc + s_ox[px];
        float y0 = floorf(py), x0 = floorf(pxf);
        float fy = py - y0, fx = pxf - x0;
        bool vy0 = (y0 >= 0.f)  && (y0 <= 63.f);
        bool vy1 = (y0 >= -1.f) && (y0 <= 62.f);
        bool vx0 = (x0 >= 0.f)  && (x0 <= 63.f);
        bool vx1 = (x0 >= -1.f) && (x0 <= 62.f);
        int iy0 = (int)fminf(fmaxf(y0,       0.f), 63.f);
        int iy1 = (int)fminf(fmaxf(y0 + 1.f, 0.f), 63.f);
        int ix0 = (int)fminf(fmaxf(x0,       0.f), 63.f);
        int ix1 = (int)fminf(fmaxf(x0 + 1.f, 0.f), 63.f);
        float w00 = (1.f - fy) * (1.f - fx) * ((vy0 && vx0) ? 1.f : 0.f);
        float w01 = (1.f - fy) * fx         * ((vy0 && vx1) ? 1.f : 0.f);
        float w10 = fy * (1.f - fx)         * ((vy1 && vx0) ? 1.f : 0.f);
        float w11 = fy * fx                 * ((vy1 && vx1) ? 1.f : 0.f);
        s_idx[s] = make_int4(iy0 * IMW + ix0, iy0 * IMW + ix1,
                             iy1 * IMW + ix0, iy1 * IMW + ix1);
        s_w[s] = make_float4(w00, w01, w10, w11);
    }
    __syncthreads();

    // per-thread constants
    const float amax = fmaxf(__uint_as_float(g_absmax[3]), 1e-20f);
    int eexp; frexpf(amax, &eexp);                 // amax = m * 2^eexp, m in [0.5,1)
    const float sB   = ldexpf(1.f, 11 - eexp);     // amax*sB in [1024, 2048)
    const float isB  = ldexpf(1.f, eexp - 11);     // exact inverse (power of 2)

    const float* xb = x + (size_t)b * CIN * PLANE;
    const int px    = tid & 63;       // B-producer px
    const int ibase = (tid >> 6) * 8; // each thread: 8 consecutive kk per 32-k half
    const int grp   = tid >> 6;
    const int bst   = px * 64 + ((grp ^ ((px >> 1) & 3)) * 16);

    const int o_tile  = (wid & 3) * 64;
    const int px_tile = (wid >> 2) * 32;
    const int arow    = o_tile + (lid & 15);
    const int arow64  = arow * 64;
    const int asw     = ((lid & 15) >> 1) & 3;
    const int ahi     = lid >> 4;
    const int brow    = px_tile + (lid & 7) + ((lid >> 4) & 1) * 8;
    const int brow64  = brow * 64;
    const int bsw     = ((brow & 31) >> 1) & 3;
    const int bsel    = (lid >> 3) & 1;

    float acc[64];
    #pragma unroll
    for (int i = 0; i < 64; i++) acc[i] = 0.f;

    // gather 8 values for 32-k half `half` of GLOBAL K64 chunk jj
    auto gather8 = [&](int jj, int half, float* v) {
        int kk = jj * 64 + half * 32 + ibase;
        int c  = kk / 9;
        int t9 = kk - c * 9;
        #pragma unroll
        for (int u = 0; u < 8; u++) {
            int r = t9 * 64 + px;
            int4   iv = s_idx[r];
            float4 wv = s_w[r];
            const float* xp = xb + (size_t)c * PLANE;
            v[u] = __ldg(xp + iv.x) * wv.x + __ldg(xp + iv.y) * wv.y
                 + __ldg(xp + iv.z) * wv.z + __ldg(xp + iv.w) * wv.w;
            if (++t9 == 9) { t9 = 0; c++; }
        }
    };
    auto storeB = [&](int buf, int half, const float* v) {
        uint32_t hw[4];
        #pragma unroll
        for (int p2 = 0; p2 < 4; p2++) {
            unsigned short h0 = __half_as_ushort(__float2half_rn(v[2 * p2]     * sB));
            unsigned short h1 = __half_as_ushort(__float2half_rn(v[2 * p2 + 1] * sB));
            hw[p2] = ((uint32_t)h1 << 16) | (uint32_t)h0;
        }
        unsigned char* bbuf = sm + SO_B + buf * BBYTES + half * BIMG;
        *(uint4*)(bbuf + bst) = make_uint4(hw[0], hw[1], hw[2], hw[3]);
    };

    // pre-loop: produce B chunk cbase (both halves) into buf 0; A in flight
    {
        float v[8];
        gather8(cbase, 0, v);
        storeB(0, 0, v);
        gather8(cbase, 1, v);
        storeB(0, 1, v);
    }
    CP_WAIT0();
    __syncthreads();

    for (int j = 0; j < NCHUNK_PER; j++) {
        // 1. prefetch A chunk j+1 (32 KB; async, no register dependency)
        if (j + 1 < NCHUNK_PER) {
            const unsigned char* src = g_wh + (size_t)(cbase + j + 1) * ABYTES;
            uint32_t dst = smb + SO_A + ((j + 1) & 1) * ABYTES;
            #pragma unroll
            for (int i = 0; i < 8; i++) {
                int idx = tid + 256 * i;
                cp16(dst + idx * 16, src + idx * 16);
            }
        }
        CP_COMMIT();

        // 2. MMA over K64 chunk j: 4 k-steps (two 32-k images)
        {
            uint32_t Ab = smb + SO_A + (j & 1) * ABYTES;
            uint32_t Bb = smb + SO_B + (j & 1) * BBYTES;
            #pragma unroll
            for (int ks4 = 0; ks4 < 4; ks4++) {
                uint32_t Abh = Ab + (ks4 >> 1) * AIMG;
                uint32_t Bbh = Bb + (ks4 >> 1) * BIMG;
                int ks = ks4 & 1;
                uint32_t bb[8];
                int bc = ((ks * 2 + bsel) ^ bsw) * 16;
                ldsm4(bb,     Bbh + brow64 + bc);
                ldsm4(bb + 4, Bbh + brow64 + 1024 + bc);
                int ac = ((ks * 2 + ahi) ^ asw) * 16;
                #pragma unroll
                for (int mt = 0; mt < 4; mt++) {
                    uint32_t a[4];
                    ldsm4(a, Abh + arow64 + mt * 1024 + ac);
                    #pragma unroll
                    for (int nt = 0; nt < 4; nt++)
                        mma_f16(acc + (mt * 4 + nt) * 4, a,
                                bb[2 * nt], bb[2 * nt + 1]);
                }
            }
        }

        // 3. gather + convert + publish B chunk j+1 (both halves) while the
        //    tensor queue drains
        if (j + 1 < NCHUNK_PER) {
            float v[8];
            gather8(cbase + j + 1, 0, v);
            storeB((j + 1) & 1, 0, v);
            gather8(cbase + j + 1, 1, v);
            storeB((j + 1) & 1, 1, v);
        }

        // 4. A(j+1) complete (own copies) + block-wide publish of A and B
        CP_WAIT0();
        __syncthreads();
    }

    // ---------------- epilogue: scale + atomic accumulate ----------------
    // out pre-filled with bias by k_binit; both K-halves RED.ADD their part.
    {
        float sdcn = fmaxf(__uint_as_float(g_absmax[2]), 1e-8f) / 7.0f;
        float sc = sdcn * isB;
        #pragma unroll
        for (int mt = 0; mt < 4; mt++) {
            int o0 = o_tile + mt * 16 + (lid >> 2);
            float* r0 = out + (((size_t)b * COUT + o0) * IMH + y) * IMW;
            float* r1 = r0 + 8 * (size_t)PLANE;
            #pragma unroll
            for (int nt = 0; nt < 4; nt++) {
                int pxo = px_tile + nt * 8 + (lid & 3) * 2;
                const float* ac = acc + (mt * 4 + nt) * 4;
                atomicAdd(r0 + pxo,     ac[0] * sc);
                atomicAdd(r0 + pxo + 1, ac[1] * sc);
                atomicAdd(r1 + pxo,     ac[2] * sc);
                atomicAdd(r1 + pxo + 1, ac[3] * sc);
            }
        }
    }
}

// ---------------- launch ----------------
extern "C" void kernel_launch(void* const* d_in, const int* in_sizes, int n_in,
                              void* d_out, int out_size) {
    const float* x       = (const float*)d_in[0];
    const float* w_off   = (const float*)d_in[1];
    const float* b_off   = (const float*)d_in[2];
    const float* w_scale = (const float*)d_in[3];
    const float* b_scale = (const float*)d_in[4];
    const float* w_dcn   = (const float*)d_in[5];
    const float* b_dcn   = (const float*)d_in[6];
    float* out = (float*)d_out;

    static bool attr_done = false;
    if (!attr_done) {
        cudaFuncSetAttribute(k_main, cudaFuncAttributeMaxDynamicSharedMemorySize,
                             SMEM_TOTAL);
        attr_done = true;
    }

    int nb = (NTOT + 255) / 256;
    k_zero<<<1, 32>>>();
    k_absmax<<<nb, 256>>>(w_off, w_scale, w_dcn);
    k_xmax<<<512, 256>>>((const float4*)x);
    k_quant<<<nb, 256>>>(w_off, w_scale, w_dcn);
    k_binit<<<(BATCH * COUT * PLANE / 4) / 256, 256>>>(out, b_dcn);
    k_offscale<<<dim3(IMH / 2, BATCH, PART_Q), 128>>>(x);
    k_main<<<dim3(IMH, BATCH, KSPLIT), 256, SMEM_TOTAL>>>(x, b_off, b_scale, out);
}